// round 16
// baseline (speedup 1.0000x reference)
#include <cuda_runtime.h>
#include <cuda_bf16.h>

// ---------------- problem-size capacities (fixed by the dataset) -------------
#define N_CAP 100000
#define E_CAP 3200000
#define F_IN  512
#define F_MID 16
#define STRIDE 96          // fixed bucket capacity per dst row (deg ~ Poisson(32))
#define NPB   256          // nodes per gemm1 block
#define KCH   16           // k-chunk staged in smem
#define XSTR  260          // xs node stride: 16B-aligned rows, 2-way STS conflicts
#define KHALF (F_IN / 2)   // 256 k per split

// ---------------- device scratch (accessed ONLY by symbol in device code) ----
// g_cnt relies on (a) zero-init of device globals at module load, (b)
// k_agg(layer=1) resetting it after use, so the zero invariant holds across
// graph replays without a dedicated zeroing kernel.
__device__ __align__(16) int   g_cnt[N_CAP];            // per-row fill count = degree
__device__ __align__(16) float g_dis[N_CAP];            // (deg+1)^-1/2
__device__ __align__(16) int   g_bkt[N_CAP * STRIDE];   // fixed-stride CSR buckets
__device__ __align__(16) float g_p0[N_CAP * F_MID];     // split-K partial 0
__device__ __align__(16) float g_p1[N_CAP * F_MID];     // split-K partial 1
__device__ __align__(16) float g_hs1[N_CAP * F_MID];    // dis ⊙ (x @ W1)
__device__ __align__(16) float g_hs2[N_CAP * F_MID];    // dis ⊙ (agg1 @ W2)

// packed f32x2 helpers (sm_103a: 2x-rate packed fp32 pipe)
#define FMA_F32X2(d, a, b, c) \
    asm("fma.rn.f32x2 %0, %1, %2, %3;" : "=l"(d) : "l"(a), "l"(b), "l"(c))
#define PACK2(d, f) \
    asm("mov.b64 %0, {%1, %1};" : "=l"(d) : "f"(f))

union F2U { unsigned long long u; float2 f; };

// ---------------- 1: MERGED kernel: split-K gemm1 blocks then fill blocks ----
// blocks [0, g1b)        : partial h1 = x[:, ksplit] @ W1[ksplit, :] (unscaled)
// blocks [g1b, g1b+fillb): bucket fill, 8 edges/thread
// gemm blocks scheduled FIRST (longest-job-first: fill backfills behind them).
__global__ __launch_bounds__(256) void k_main(const float* __restrict__ x,
                                              const float* __restrict__ w,
                                              const int* __restrict__ ei,
                                              int E, int N, int g1b) {
    __shared__ __align__(16) float xs[KCH * XSTR];                  // 16.6 KB
    __shared__ __align__(16) unsigned long long wd[KCH * F_MID];    // 2 KB, W dup

    if (blockIdx.x >= g1b) {
        // ---------------- fill branch, 8 edges/thread ----------------
        int t = (blockIdx.x - g1b) * blockDim.x + threadIdx.x;
        int e8 = t * 8;
        if (e8 + 7 < E) {
#pragma unroll
            for (int q = 0; q < 2; q++) {
                int4 s4 = *(const int4*)(ei + e8 + q * 4);
                int4 d4 = *(const int4*)(ei + E + e8 + q * 4);
                int slot;
                if ((unsigned)d4.x < (unsigned)N && (unsigned)s4.x < (unsigned)N) {
                    slot = atomicAdd(&g_cnt[d4.x], 1);
                    if (slot < STRIDE) g_bkt[d4.x * STRIDE + slot] = s4.x;
                }
                if ((unsigned)d4.y < (unsigned)N && (unsigned)s4.y < (unsigned)N) {
                    slot = atomicAdd(&g_cnt[d4.y], 1);
                    if (slot < STRIDE) g_bkt[d4.y * STRIDE + slot] = s4.y;
                }
                if ((unsigned)d4.z < (unsigned)N && (unsigned)s4.z < (unsigned)N) {
                    slot = atomicAdd(&g_cnt[d4.z], 1);
                    if (slot < STRIDE) g_bkt[d4.z * STRIDE + slot] = s4.z;
                }
                if ((unsigned)d4.w < (unsigned)N && (unsigned)s4.w < (unsigned)N) {
                    slot = atomicAdd(&g_cnt[d4.w], 1);
                    if (slot < STRIDE) g_bkt[d4.w * STRIDE + slot] = s4.w;
                }
            }
        } else if (e8 < E) {
            for (int e = e8; e < E; e++) {
                int s = ei[e];
                int d = ei[E + e];
                if ((unsigned)d < (unsigned)N && (unsigned)s < (unsigned)N) {
                    int slot = atomicAdd(&g_cnt[d], 1);
                    if (slot < STRIDE) g_bkt[d * STRIDE + slot] = s;
                }
            }
        }
        return;
    }

    // ---------------- split-K gemm1 branch (node-pair packed, W dup) ---------
    int split = blockIdx.x & 1;               // interleaved split co-scheduling
    int nblk  = blockIdx.x >> 1;
    int kbase = split * KHALF;
    float* hp = split ? g_p1 : g_p0;

    int t  = threadIdx.x;
    int n0 = nblk * NPB;
    int r  = t >> 2;     // staging row 0..63
    int c  = t & 3;      // staging col group
    int ng = t >> 2;     // node group (4 nodes = 2 packed pairs)
    int jg = t & 3;      // feature group (4 features)

    // prefetch chunk 0: x tile + this chunk's W row block
    float4 buf[4];
#pragma unroll
    for (int p = 0; p < 4; p++) {
        int n = n0 + p * 64 + r;
        buf[p] = (n < N) ? __ldg((const float4*)(x + (size_t)n * F_IN + kbase + c * 4))
                         : make_float4(0.f, 0.f, 0.f, 0.f);
    }
    float wbuf = __ldg(&w[(size_t)kbase * F_MID + t]);   // w[k0..k0+16)x[0..16)

    unsigned long long acc[2][4];   // [node pair][feature j]
#pragma unroll
    for (int P = 0; P < 2; P++)
#pragma unroll
        for (int j = 0; j < 4; j++) acc[P][j] = 0ull;

    for (int chunk = 0; chunk < KHALF / KCH; chunk++) {
        __syncthreads();
        // transposed STS of x tile (2-way conflicts, XSTR=260)
#pragma unroll
        for (int p = 0; p < 4; p++) {
            int row = p * 64 + r;
            xs[(c * 4 + 0) * XSTR + row] = buf[p].x;
            xs[(c * 4 + 1) * XSTR + row] = buf[p].y;
            xs[(c * 4 + 2) * XSTR + row] = buf[p].z;
            xs[(c * 4 + 3) * XSTR + row] = buf[p].w;
        }
        // duplicated W: wd[k_local*16 + j] = (w,w); t = k_local*16 + j
        { unsigned long long wp; PACK2(wp, wbuf); wd[t] = wp; }
        __syncthreads();

        // prefetch next chunk (overlaps compute)
        if (chunk + 1 < KHALF / KCH) {
            int k0n = kbase + (chunk + 1) * KCH;
#pragma unroll
            for (int p = 0; p < 4; p++) {
                int n = n0 + p * 64 + r;
                buf[p] = (n < N) ? __ldg((const float4*)(x + (size_t)n * F_IN + k0n + c * 4))
                                 : make_float4(0.f, 0.f, 0.f, 0.f);
            }
            wbuf = __ldg(&w[(size_t)k0n * F_MID + t]);
        }

#pragma unroll
        for (int k = 0; k < KCH; k++) {
            // 4 nodes as 2 naturally-packed f32x2 pairs (plain-float smem)
            ulonglong2 xp = *(const ulonglong2*)(xs + k * XSTR + ng * 4);
            // 4 duplicated W values for features jg*4..+4
            ulonglong2 w01 = *(const ulonglong2*)(wd + k * F_MID + jg * 4);
            ulonglong2 w23 = *(const ulonglong2*)(wd + k * F_MID + jg * 4 + 2);
            FMA_F32X2(acc[0][0], xp.x, w01.x, acc[0][0]);
            FMA_F32X2(acc[0][1], xp.x, w01.y, acc[0][1]);
            FMA_F32X2(acc[0][2], xp.x, w23.x, acc[0][2]);
            FMA_F32X2(acc[0][3], xp.x, w23.y, acc[0][3]);
            FMA_F32X2(acc[1][0], xp.y, w01.x, acc[1][0]);
            FMA_F32X2(acc[1][1], xp.y, w01.y, acc[1][1]);
            FMA_F32X2(acc[1][2], xp.y, w23.x, acc[1][2]);
            FMA_F32X2(acc[1][3], xp.y, w23.y, acc[1][3]);
        }
    }

    // epilogue: unpack node halves, store UNSCALED partial 16B per (node, jg)
#pragma unroll
    for (int P = 0; P < 2; P++) {
#pragma unroll
        for (int h = 0; h < 2; h++) {
            int n = n0 + ng * 4 + 2 * P + h;
            if (n < N) {
                F2U u0, u1, u2, u3;
                u0.u = acc[P][0]; u1.u = acc[P][1]; u2.u = acc[P][2]; u3.u = acc[P][3];
                float4 o;
                o.x = h ? u0.f.y : u0.f.x;
                o.y = h ? u1.f.y : u1.f.x;
                o.z = h ? u2.f.y : u2.f.x;
                o.w = h ? u3.f.y : u3.f.x;
                *(float4*)(hp + (size_t)n * 16 + jg * 4) = o;
            }
        }
    }
}

// ---------------- 2: combine split-K partials, compute dis, scale -----------
__global__ void k_finscale(int N) {
    int i = blockIdx.x * blockDim.x + threadIdx.x;
    int node = i >> 2;
    int f    = i & 3;
    if (node >= N) return;
    float dd = rsqrtf((float)(g_cnt[node] + 1));   // + self loop
    if (f == 0) g_dis[node] = dd;
    size_t off = (size_t)node * 16 + f * 4;
    float4 a = *(const float4*)(g_p0 + off);
    float4 b = *(const float4*)(g_p1 + off);
    float4 v;
    v.x = dd * (a.x + b.x);
    v.y = dd * (a.y + b.y);
    v.z = dd * (a.z + b.z);
    v.w = dd * (a.w + b.w);
    *(float4*)(g_hs1 + off) = v;
}

// ---------------- 3/4: aggregation, 2 dst nodes per warp, idx-pipelined ------
// halfwarp h = lane>>4 owns node d = warp*2+h; within 16 lanes:
// sl = (lane>>2)&3 (4 edge slots), f = lane&3 (float4 feature group).
// Main loop: 16 edges/iter (4 independent row-gather chains) with next-iter
// index prefetch. layer 1 resets g_cnt[d]=0 after use (replaces k_zero).
__global__ __launch_bounds__(256) void k_agg(int layer, const float* __restrict__ w2,
                                             float* __restrict__ out, int N) {
    __shared__ float wt[256];
    if (layer == 0 && threadIdx.x < 256) wt[threadIdx.x] = w2[threadIdx.x];
    if (layer == 0) __syncthreads();

    int warp = (blockIdx.x * blockDim.x + threadIdx.x) >> 5;
    int lane = threadIdx.x & 31;
    int half = lane >> 4;
    int d    = warp * 2 + half;
    if (d >= N) return;

    const float* hs = (layer == 0) ? g_hs1 : g_hs2;

    int start = d * STRIDE;
    int cnt   = g_cnt[d];
    if (layer == 1 && lane == (half << 4)) g_cnt[d] = 0;   // restore zero invariant
    if (cnt > STRIDE) cnt = STRIDE;
    int sl = (lane >> 2) & 3;   // edge slot 0..3 within halfwarp
    int f  = lane & 3;          // feature group: floats [4f, 4f+4)

    float ax = 0.f, ay = 0.f, az = 0.f, aw = 0.f;

    int base = 0;
    int iA = 0, iB = 0, iC = 0, iD = 0;
    if (base + 16 <= cnt) {                 // preload iteration 0 indices
        iA = __ldg(&g_bkt[start + sl]);
        iB = __ldg(&g_bkt[start + 4 + sl]);
        iC = __ldg(&g_bkt[start + 8 + sl]);
        iD = __ldg(&g_bkt[start + 12 + sl]);
    }
    // 16 edges per iteration per node: 4 independent L2 chains per lane
    for (; base + 16 <= cnt; base += 16) {
        int nA = iA, nB = iB, nC = iC, nD = iD;
        if (base + 32 <= cnt) {             // prefetch next indices
            iA = __ldg(&g_bkt[start + base + 16 + sl]);
            iB = __ldg(&g_bkt[start + base + 20 + sl]);
            iC = __ldg(&g_bkt[start + base + 24 + sl]);
            iD = __ldg(&g_bkt[start + base + 28 + sl]);
        }
        float4 vA = __ldg((const float4*)(hs + (size_t)nA * 16 + f * 4));
        float4 vB = __ldg((const float4*)(hs + (size_t)nB * 16 + f * 4));
        float4 vC = __ldg((const float4*)(hs + (size_t)nC * 16 + f * 4));
        float4 vD = __ldg((const float4*)(hs + (size_t)nD * 16 + f * 4));
        ax += (vA.x + vB.x) + (vC.x + vD.x);
        ay += (vA.y + vB.y) + (vC.y + vD.y);
        az += (vA.z + vB.z) + (vC.z + vD.z);
        aw += (vA.w + vB.w) + (vC.w + vD.w);
    }
    for (; base + 8 <= cnt; base += 8) {
        int sA = __ldg(&g_bkt[start + base + sl]);
        int sB = __ldg(&g_bkt[start + base + 4 + sl]);
        float4 vA = __ldg((const float4*)(hs + (size_t)sA * 16 + f * 4));
        float4 vB = __ldg((const float4*)(hs + (size_t)sB * 16 + f * 4));
        ax += vA.x + vB.x; ay += vA.y + vB.y;
        az += vA.z + vB.z; aw += vA.w + vB.w;
    }
    for (; base < cnt; base += 4) {
        if (base + sl < cnt) {
            int s = __ldg(&g_bkt[start + base + sl]);
            float4 v = __ldg((const float4*)(hs + (size_t)s * 16 + f * 4));
            ax += v.x; ay += v.y; az += v.z; aw += v.w;
        }
    }
    // reduce across the 4 slots (xor 4, 8 stays within the 16-lane half)
#pragma unroll
    for (int off = 4; off <= 8; off <<= 1) {
        ax += __shfl_xor_sync(0xffffffffu, ax, off);
        ay += __shfl_xor_sync(0xffffffffu, ay, off);
        az += __shfl_xor_sync(0xffffffffu, az, off);
        aw += __shfl_xor_sync(0xffffffffu, aw, off);
    }

    // self loop (pre-scaled), then scale by dis[d]
    float4 sv = __ldg((const float4*)(hs + (size_t)d * 16 + f * 4));
    float dd = g_dis[d];
    float tx = dd * (ax + sv.x);
    float ty = dd * (ay + sv.y);
    float tz = dd * (az + sv.z);
    float tw = dd * (aw + sv.w);

    if (layer == 0) {
        // fused GEMM2: feature i of this node lives in component i&3 of
        // absolute lane (half<<4) + (i>>2). Each of the 16 lanes computes j.
        int j = lane & 15;
        int lb = half << 4;
        float h2 = 0.f;
#pragma unroll
        for (int i = 0; i < 16; i++) {
            float cc = ((i & 3) == 0) ? tx : ((i & 3) == 1) ? ty : ((i & 3) == 2) ? tz : tw;
            float ti = __shfl_sync(0xffffffffu, cc, lb + (i >> 2));
            h2 += ti * wt[i * 16 + j];
        }
        g_hs2[(size_t)d * 16 + j] = dd * h2;   // all 32 lanes: 128B per warp
    } else {
        if (sl == 0) {   // lanes {0..3} and {16..19} store float4 rows
            float4 o; o.x = tx; o.y = ty; o.z = tz; o.w = tw;
            *((float4*)(out + (size_t)d * 16 + f * 4)) = o;
        }
    }
}

// ---------------- launch ----------------
extern "C" void kernel_launch(void* const* d_in, const int* in_sizes, int n_in,
                              void* d_out, int out_size) {
    const float* x   = (const float*)d_in[0];
    const int*   ei  = (const int*)d_in[1];     // int32 (JAX x64 disabled)
    const float* w1  = (const float*)d_in[2];
    const float* w2  = (const float*)d_in[3];
    float*       out = (float*)d_out;

    int N = in_sizes[0] / F_IN;   // 100000
    int E = in_sizes[1] / 2;      // 3200000
    int E8 = (E + 7) / 8;

    int g1b   = 2 * ((N + NPB - 1) / NPB);  // 782 split-K gemm1 blocks (first)
    int fillb = (E8 + 255) / 256;           // 1563 fill blocks (backfill)

    k_main    <<<g1b + fillb, 256>>>(x, w1, ei, E, N, g1b);   // overlapped fill+gemm1
    k_finscale<<<(N * 4 + 255) / 256, 256>>>(N);

    int aggw = (N + 1) / 2;                  // warps (2 nodes each)
    k_agg<<<(aggw * 32 + 255) / 256, 256>>>(0, w2, out, N);
    k_agg<<<(aggw * 32 + 255) / 256, 256>>>(1, w2, out, N);
}